// round 6
// baseline (speedup 1.0000x reference)
#include <cuda_runtime.h>
#include <cuda_bf16.h>
#include <cstdint>

#define N_NODES 50000
#define D_FEAT  128
#define N_EDGES 600000
#define CAP     96      // per-node bucket capacity (Poisson(12) max in-deg ~40)

// static scratch (no cudaMalloc allowed). Zero-initialized at module load;
// agg_kernel re-zeroes g_cnt after use so every kernel_launch call (first
// correctness run and every graph replay) starts from zeroed counters.
__device__ int g_cnt[N_NODES];
__device__ int g_bucket[N_NODES * CAP];

// ---------------------------------------------------------------------------
// Kernel 1: bin edges by destination. One thread per edge.
// Index dtype detected per-block by warp 0 (ballot over 32 int32 pairs):
// int64 values < 2^31 read as int32 pairs give (val, 0); for int32 data the
// odd words are random node ids, so all-32-lanes-match is conclusive.
// ---------------------------------------------------------------------------
__global__ void fill_kernel(const void* __restrict__ src_raw,
                            const void* __restrict__ dst_raw) {
    __shared__ int sh_is64;
    {
        int tid = threadIdx.x;
        if (tid < 32) {
            const int* p = (const int*)dst_raw;
            int lo = p[2 * tid];
            int hi = p[2 * tid + 1];
            bool ok = (hi == 0) && (lo >= 0) && (lo < N_NODES);
            unsigned m = __ballot_sync(0xffffffffu, ok);
            if (tid == 0) sh_is64 = (m == 0xffffffffu) ? 1 : 0;
        }
    }
    __syncthreads();
    int is64 = sh_is64;

    int e = blockIdx.x * blockDim.x + threadIdx.x;
    if (e >= N_EDGES) return;

    long long s, d;
    if (is64) {
        s = __ldg((const long long*)src_raw + e);
        d = __ldg((const long long*)dst_raw + e);
    } else {
        s = __ldg((const int*)src_raw + e);
        d = __ldg((const int*)dst_raw + e);
    }
    if (s < 0 || s >= N_NODES || d < 0 || d >= N_NODES) return;

    int pos = atomicAdd(&g_cnt[(int)d], 1);
    if (pos < CAP) g_bucket[(int)d * CAP + pos] = (int)s;
}

// ---------------------------------------------------------------------------
// Overflow recovery (never taken for this dataset: c <= ~40 << CAP).
// Kept out-of-line so the agg mainline stays at low register count.
// Recomputes the full sum for this node by scanning the edge list.
// ---------------------------------------------------------------------------
__device__ __noinline__ float4 overflow_rescan(const float* emb,
                                               const void* src_raw,
                                               const void* dst_raw,
                                               int node, int lane) {
    // re-detect dtype locally (cheap; this path is cold)
    const int* p = (const int*)dst_raw;
    bool is64 = true;
    for (int k = 0; k < 8; k++) {
        int lo = p[2 * k], hi = p[2 * k + 1];
        if (hi != 0 || lo < 0 || lo >= N_NODES) { is64 = false; break; }
    }
    float4 acc = make_float4(0.f, 0.f, 0.f, 0.f);
    for (int e = 0; e < N_EDGES; e++) {
        long long d = is64 ? __ldg((const long long*)dst_raw + e)
                           : (long long)__ldg((const int*)dst_raw + e);
        if ((int)d != node) continue;
        long long s = is64 ? __ldg((const long long*)src_raw + e)
                           : (long long)__ldg((const int*)src_raw + e);
        if (s < 0 || s >= N_NODES) continue;
        float4 v = __ldg((const float4*)(emb + s * D_FEAT) + lane);
        acc.x += v.x; acc.y += v.y; acc.z += v.z; acc.w += v.w;
    }
    return acc;
}

// ---------------------------------------------------------------------------
// Kernel 2: one warp per node. Gather-reduce bucketed sources (L2-resident
// table), write the mean once, then reset this node's counter for the next
// replay.
// ---------------------------------------------------------------------------
__global__ void agg_kernel(const float* __restrict__ emb,
                           float* __restrict__ out,
                           const void* __restrict__ src_raw,
                           const void* __restrict__ dst_raw) {
    int gtid = blockIdx.x * blockDim.x + threadIdx.x;
    int node = gtid >> 5;
    int lane = gtid & 31;
    if (node >= N_NODES) return;

    int c = g_cnt[node];
    if (lane == 0) g_cnt[node] = 0;   // reset for next graph replay

    int m = (c < CAP) ? c : CAP;
    const int* bk = g_bucket + node * CAP;

    float4 acc = make_float4(0.f, 0.f, 0.f, 0.f);

    for (int base = 0; base < m; base += 32) {
        int lim = m - base; if (lim > 32) lim = 32;
        int s_l = (lane < lim) ? bk[base + lane] : 0;
        #pragma unroll 4
        for (int e = 0; e < lim; e++) {
            int s = __shfl_sync(0xffffffffu, s_l, e);
            float4 v = __ldg((const float4*)(emb + (long long)s * D_FEAT) + lane);
            acc.x += v.x; acc.y += v.y; acc.z += v.z; acc.w += v.w;
        }
    }

    if (__builtin_expect(c > CAP, 0)) {
        acc = overflow_rescan(emb, src_raw, dst_raw, node, lane);
    }

    float inv = (c > 0) ? (1.0f / (float)c) : 0.0f;
    acc.x *= inv; acc.y *= inv; acc.z *= inv; acc.w *= inv;
    ((float4*)out)[node * (D_FEAT / 4) + lane] = acc;
}

// ---------------------------------------------------------------------------
extern "C" void kernel_launch(void* const* d_in, const int* in_sizes, int n_in,
                              void* d_out, int out_size) {
    const float* emb = (const float*)d_in[0];
    const void*  src = d_in[1];
    const void*  dst = d_in[2];
    float* out = (float*)d_out;

    fill_kernel<<<(N_EDGES + 255) / 256, 256>>>(src, dst);
    {
        long long total_threads = (long long)N_NODES * 32;
        agg_kernel<<<(int)((total_threads + 255) / 256), 256>>>(emb, out, src, dst);
    }
}

// round 7
// speedup vs baseline: 1.1817x; 1.1817x over previous
#include <cuda_runtime.h>
#include <cuda_bf16.h>
#include <cstdint>

#define N_NODES 50000
#define D_FEAT  128
#define N_EDGES 600000
#define CAP     96   // Poisson(12) in-degree: P(deg > 96) ~ 1e-60 -> never overflows

// static scratch (no cudaMalloc allowed). Zero-initialized at module load;
// agg_kernel re-zeroes g_cnt after consuming it, so the correctness call and
// every graph replay start from zeroed counters.
__device__ int g_cnt[N_NODES];
__device__ int g_bucket[N_NODES * CAP];

// ---------------------------------------------------------------------------
// Kernel 1: bin edges by destination. One thread per edge.
// Index dtype detected per-block by warp 0 via ballot over 32 int32 pairs:
// int64 values < 2^31 read as int32 pairs give (val, 0); for int32 data the
// odd words are random node ids, so all-32-lanes-consistent is conclusive.
// ---------------------------------------------------------------------------
__global__ void fill_kernel(const void* __restrict__ src_raw,
                            const void* __restrict__ dst_raw) {
    __shared__ int sh_is64;
    if (threadIdx.x < 32) {
        const int* p = (const int*)dst_raw;
        int lo = p[2 * threadIdx.x];
        int hi = p[2 * threadIdx.x + 1];
        bool ok = (hi == 0) && (lo >= 0) && (lo < N_NODES);
        unsigned m = __ballot_sync(0xffffffffu, ok);
        if (threadIdx.x == 0) sh_is64 = (m == 0xffffffffu) ? 1 : 0;
    }
    __syncthreads();
    int is64 = sh_is64;

    int e = blockIdx.x * blockDim.x + threadIdx.x;
    if (e >= N_EDGES) return;

    long long s, d;
    if (is64) {
        s = __ldg((const long long*)src_raw + e);
        d = __ldg((const long long*)dst_raw + e);
    } else {
        s = __ldg((const int*)src_raw + e);
        d = __ldg((const int*)dst_raw + e);
    }
    if (s < 0 || s >= N_NODES || d < 0 || d >= N_NODES) return;

    int pos = atomicAdd(&g_cnt[(int)d], 1);
    if (pos < CAP) g_bucket[(int)d * CAP + pos] = (int)s;
}

// ---------------------------------------------------------------------------
// Kernel 2: one warp per node. Gather-reduce bucketed sources (table is
// L2-resident: 25.6 MB), write the mean once. Leaf kernel, minimal args —
// keeps regs ~32 and the gather loop MLP-pipelined (R6 showed any ABI call /
// extra pointer args here serializes the loads: 26.7us -> 81.7us).
// ---------------------------------------------------------------------------
__global__ void agg_kernel(const float* __restrict__ emb,
                           float* __restrict__ out) {
    int gtid = blockIdx.x * blockDim.x + threadIdx.x;
    int node = gtid >> 5;
    int lane = gtid & 31;
    if (node >= N_NODES) return;

    int c = g_cnt[node];
    if (lane == 0) g_cnt[node] = 0;   // reset for next replay

    int m = (c < CAP) ? c : CAP;      // clamp (never hit for this dataset)
    const int* bk = g_bucket + node * CAP;

    float4 acc = make_float4(0.f, 0.f, 0.f, 0.f);

    for (int base = 0; base < m; base += 32) {
        int lim = m - base; if (lim > 32) lim = 32;
        int s_l = (lane < lim) ? bk[base + lane] : 0;
        #pragma unroll 4
        for (int e = 0; e < lim; e++) {
            int s = __shfl_sync(0xffffffffu, s_l, e);
            float4 v = __ldg((const float4*)(emb + (long long)s * D_FEAT) + lane);
            acc.x += v.x; acc.y += v.y; acc.z += v.z; acc.w += v.w;
        }
    }

    float inv = (c > 0) ? (1.0f / (float)c) : 0.0f;
    acc.x *= inv; acc.y *= inv; acc.z *= inv; acc.w *= inv;
    ((float4*)out)[node * (D_FEAT / 4) + lane] = acc;
}

// ---------------------------------------------------------------------------
extern "C" void kernel_launch(void* const* d_in, const int* in_sizes, int n_in,
                              void* d_out, int out_size) {
    const float* emb = (const float*)d_in[0];
    const void*  src = d_in[1];
    const void*  dst = d_in[2];
    float* out = (float*)d_out;

    fill_kernel<<<(N_EDGES + 255) / 256, 256>>>(src, dst);
    {
        long long total_threads = (long long)N_NODES * 32;
        agg_kernel<<<(int)((total_threads + 255) / 256), 256>>>(emb, out);
    }
}

// round 8
// speedup vs baseline: 2.1331x; 1.8052x over previous
#include <cuda_runtime.h>
#include <cuda_bf16.h>
#include <cstdint>

#define N_NODES 50000
#define D_FEAT  128
#define N_EDGES 600000
#define CAP     96   // Poisson(12) in-degree: P(deg > 96) ~ 1e-60 -> never overflows

// static scratch (no cudaMalloc allowed). Zero-initialized at module load;
// agg_kernel re-zeroes g_cnt in its tail so the correctness call and every
// graph replay start from zeroed counters.
__device__ int g_cnt[N_NODES];
__device__ int g_bucket[N_NODES * CAP];

// ---------------------------------------------------------------------------
// Kernel 1: bin edges by destination. One thread per edge.
// Index dtype detected per-block by warp 0 via ballot over 32 int32 pairs:
// int64 values < 2^31 read as int32 pairs give (val, 0); for int32 data the
// odd words are random node ids, so all-32-lanes-consistent is conclusive.
// ---------------------------------------------------------------------------
__global__ void fill_kernel(const void* __restrict__ src_raw,
                            const void* __restrict__ dst_raw) {
    __shared__ int sh_is64;
    if (threadIdx.x < 32) {
        const int* p = (const int*)dst_raw;
        int lo = p[2 * threadIdx.x];
        int hi = p[2 * threadIdx.x + 1];
        bool ok = (hi == 0) && (lo >= 0) && (lo < N_NODES);
        unsigned m = __ballot_sync(0xffffffffu, ok);
        if (threadIdx.x == 0) sh_is64 = (m == 0xffffffffu) ? 1 : 0;
    }
    __syncthreads();
    int is64 = sh_is64;

    int e = blockIdx.x * blockDim.x + threadIdx.x;
    if (e >= N_EDGES) return;

    long long s, d;
    if (is64) {
        s = __ldg((const long long*)src_raw + e);
        d = __ldg((const long long*)dst_raw + e);
    } else {
        s = __ldg((const int*)src_raw + e);
        d = __ldg((const int*)dst_raw + e);
    }
    if (s < 0 || s >= N_NODES || d < 0 || d >= N_NODES) return;

    int pos = atomicAdd(&g_cnt[(int)d], 1);
    if (pos < CAP) g_bucket[(int)d * CAP + pos] = (int)s;
}

// ---------------------------------------------------------------------------
// Kernel 2: one warp per node. Gather-reduce bucketed sources (table is
// L2-resident: 25.6 MB), write the mean once.
// CRITICAL scheduling notes learned from R6/R7 regressions:
//   - must be a leaf kernel with only (emb, out) args (no ABI calls)
//   - NO branch/store between the count load and the gather loop — the
//     predicated reset store lives in the kernel TAIL, after the output
//     store, so the loop's load batching (MLP) is undisturbed.
// ---------------------------------------------------------------------------
__global__ void agg_kernel(const float* __restrict__ emb,
                           float* __restrict__ out) {
    int gtid = blockIdx.x * blockDim.x + threadIdx.x;
    int node = gtid >> 5;
    int lane = gtid & 31;
    if (node >= N_NODES) return;

    int c = g_cnt[node];
    int m = (c < CAP) ? c : CAP;   // clamp (never hit for this dataset)
    const int* bk = g_bucket + node * CAP;

    float4 acc = make_float4(0.f, 0.f, 0.f, 0.f);

    for (int base = 0; base < m; base += 32) {
        int lim = m - base; if (lim > 32) lim = 32;
        int s_l = (lane < lim) ? bk[base + lane] : 0;
        #pragma unroll 4
        for (int e = 0; e < lim; e++) {
            int s = __shfl_sync(0xffffffffu, s_l, e);
            float4 v = __ldg((const float4*)(emb + (long long)s * D_FEAT) + lane);
            acc.x += v.x; acc.y += v.y; acc.z += v.z; acc.w += v.w;
        }
    }

    float inv = (c > 0) ? (1.0f / (float)c) : 0.0f;
    acc.x *= inv; acc.y *= inv; acc.z *= inv; acc.w *= inv;
    ((float4*)out)[node * (D_FEAT / 4) + lane] = acc;

    // tail: reset counter for the next graph replay (after all loop loads)
    if (lane == 0) g_cnt[node] = 0;
}

// ---------------------------------------------------------------------------
extern "C" void kernel_launch(void* const* d_in, const int* in_sizes, int n_in,
                              void* d_out, int out_size) {
    const float* emb = (const float*)d_in[0];
    const void*  src = d_in[1];
    const void*  dst = d_in[2];
    float* out = (float*)d_out;

    fill_kernel<<<(N_EDGES + 255) / 256, 256>>>(src, dst);
    {
        long long total_threads = (long long)N_NODES * 32;
        agg_kernel<<<(int)((total_threads + 255) / 256), 256>>>(emb, out);
    }
}